// round 5
// baseline (speedup 1.0000x reference)
#include <cuda_runtime.h>
#include <cstdint>

// CorticalSheet fixed-degree SpMM
//   out[n,b] = sum_k values[n,k] * x[indices[n,k], b] + bias[n]
// N derived from in_sizes (1,000,000), K = 32, B = 8
//
// One warp per neuron, 2 gathered rows per LDG (replay-minimized):
//   - R4 ncu showed L1tex wavefront throughput binding (L1=83.9%), with the
//     4-rows-per-LDG layout paying 3 within-instruction replay wavefronts
//     (~2.07 cyc each) per gather LDG. This version uses 16 lanes per row
//     (2-way broadcast of each of the 8 floats), so each gather LDG touches
//     only 2 distinct lines -> 1 replay instead of 3.
//     Modeled L1 cost/neuron: 16*(1+2.07) ~= 49 cyc vs 8*(1+3*2.07) ~= 58.
//   - Lane layout: half = lane>>4 (even/odd k), rep = (lane>>3)&1 (redundant
//     replica, makes the row read a clean 2-way broadcast), b = lane&7.
//   - Per step s (0..15): k = 2s + half, idx/v broadcast via one
//     variable-source shfl each; one LDG.32; one FMA.
//   - Reduction: single shfl_xor(16) combines even/odd halves; lanes 0..7
//     store the 8 outputs (one 32B sector per neuron).

#define KK 32
#define BB 8

__global__ __launch_bounds__(256, 4)
void cortical_spmm_kernel(const float*  __restrict__ x,
                          const float*  __restrict__ values,
                          const float*  __restrict__ bias,
                          const int*    __restrict__ indices,
                          float*        __restrict__ out,
                          int N)
{
    const unsigned FULL = 0xffffffffu;
    const int warp_global = (int)((blockIdx.x * (unsigned)blockDim.x + threadIdx.x) >> 5);
    if (warp_global >= N) return;
    const int n    = warp_global;
    const int lane = (int)(threadIdx.x & 31u);

    // Bias load early (uniform address -> broadcast), overlaps gather chain.
    const float bn = __ldg(bias + n);

    // Coalesced streaming loads of this neuron's synapse data (evict-first:
    // protect x's L2 residency).
    const int   idx_mine = __ldcs(indices + (size_t)n * KK + lane);
    const float val_mine = __ldcs(values  + (size_t)n * KK + lane);

    const int half = lane >> 4;     // 0: even k, 1: odd k
    const int b    = lane & 7;      // output column

    // Per-lane base pointer: fold b into the address once.
    const float* xb = x + b;

    float acc = 0.0f;
#pragma unroll
    for (int s = 0; s < 16; ++s) {
        const int   k   = 2 * s + half;                    // per-lane source k
        const int   idx = __shfl_sync(FULL, idx_mine, k);  // variable-source shfl
        const float v   = __shfl_sync(FULL, val_mine, k);
        const float xv  = __ldg(xb + (size_t)idx * BB);    // 2 lines per LDG
        acc = fmaf(v, xv, acc);
    }

    // Combine even-k half (lanes 0..15) with odd-k half (lanes 16..31).
    acc += __shfl_xor_sync(FULL, acc, 16);

    if (lane < 8) {
        out[(size_t)n * BB + b] = acc + bn;
    }
}

extern "C" void kernel_launch(void* const* d_in, const int* in_sizes, int n_in,
                              void* d_out, int out_size)
{
    // metadata order: x [N*B] f32, values [N*K] f32, bias [N] f32, indices [N*K] i32
    const float* x       = (const float*)d_in[0];
    const float* values  = (const float*)d_in[1];
    const float* bias    = (const float*)d_in[2];
    const int*   indices = (const int*)d_in[3];
    float*       out     = (float*)d_out;

    const int N = in_sizes[2];  // bias element count == number of neurons

    const int threads = 256;
    const int warps_per_block = threads / 32;
    const int blocks = (N + warps_per_block - 1) / warps_per_block;

    cortical_spmm_kernel<<<blocks, threads>>>(x, values, bias, indices, out, N);
}

// round 6
// speedup vs baseline: 1.6448x; 1.6448x over previous
#include <cuda_runtime.h>
#include <cstdint>

// CorticalSheet fixed-degree SpMM
//   out[n,b] = sum_k values[n,k] * x[indices[n,k], b] + bias[n]
// N from in_sizes (1,000,000), K = 32, B = 8
//
// One warp per neuron, SHUFFLE-FREE hot loop (R5 post-mortem: SHFL shares the
// L1tex/MIO pipe; R4 spent ~29% of the binding pipe on broadcasts).
//
//   - k -> lane remap: lane = kgroup*8 + b. Lane's kgroup owns the contiguous
//     k-range [8*kgroup, 8*kgroup+8), self-loaded as two int4 (indices) and
//     two float4 (values). The 8 lanes of a kgroup share each address and all
//     4 kgroup addresses sit in ONE 128B line -> each of these 4 stream loads
//     is a single L1 wavefront (in-line broadcast), same cost as R4's
//     coalesced loads but with zero SHFLs afterward.
//   - Gather geometry identical to R4 (the measured best): per step the 4
//     kgroups read 4 random 32B rows, 8 lanes per row = 1 sector per row,
//     4 lines per LDG, 8 LDGs -> the 32-wavefront/neuron floor.
//   - Reduction: shfl_xor(8) + shfl_xor(16) over kgroups; lanes 0..7 store
//     the 8 outputs (one 32B sector).
//   - __launch_bounds__(256, 6) caps regs at 42 to protect occupancy (~75%)
//     against the 16 live idx/val registers.

#define KK 32
#define BB 8

__global__ __launch_bounds__(256, 6)
void cortical_spmm_kernel(const float*  __restrict__ x,
                          const float*  __restrict__ values,
                          const float*  __restrict__ bias,
                          const int*    __restrict__ indices,
                          float*        __restrict__ out,
                          int N)
{
    const unsigned FULL = 0xffffffffu;
    const int warp_global = (int)((blockIdx.x * (unsigned)blockDim.x + threadIdx.x) >> 5);
    if (warp_global >= N) return;
    const int n    = warp_global;
    const int lane = (int)(threadIdx.x & 31u);

    const int kgroup = lane >> 3;   // 0..3: owns k in [8*kgroup, 8*kgroup+8)
    const int b      = lane & 7;    // output column

    // Bias early (uniform address -> broadcast), overlaps the gather chain.
    const float bn = __ldg(bias + n);

    // Self-service streaming loads: each lane loads exactly the 8 (idx, val)
    // pairs it will consume. 4 distinct 16B addresses per instruction, all in
    // one 128B line -> 1 wavefront each, evict-first to protect x in L2.
    const int4*   ip = (const int4*)  (indices + (size_t)n * KK + kgroup * 8);
    const float4* vp = (const float4*)(values  + (size_t)n * KK + kgroup * 8);
    const int4   i0 = __ldcs(ip);
    const int4   i1 = __ldcs(ip + 1);
    const float4 v0 = __ldcs(vp);
    const float4 v1 = __ldcs(vp + 1);

    const float* xb = x + b;

    // 8 independent gathers, batched for MLP=8; 4 random rows per LDG.
    const float x0 = __ldg(xb + (size_t)i0.x * BB);
    const float x1 = __ldg(xb + (size_t)i0.y * BB);
    const float x2 = __ldg(xb + (size_t)i0.z * BB);
    const float x3 = __ldg(xb + (size_t)i0.w * BB);
    const float x4 = __ldg(xb + (size_t)i1.x * BB);
    const float x5 = __ldg(xb + (size_t)i1.y * BB);
    const float x6 = __ldg(xb + (size_t)i1.z * BB);
    const float x7 = __ldg(xb + (size_t)i1.w * BB);

    float acc = v0.x * x0;
    acc = fmaf(v0.y, x1, acc);
    acc = fmaf(v0.z, x2, acc);
    acc = fmaf(v0.w, x3, acc);
    acc = fmaf(v1.x, x4, acc);
    acc = fmaf(v1.y, x5, acc);
    acc = fmaf(v1.z, x6, acc);
    acc = fmaf(v1.w, x7, acc);

    // Reduce across the 4 kgroups (lanes b, b+8, b+16, b+24).
    acc += __shfl_xor_sync(FULL, acc, 8);
    acc += __shfl_xor_sync(FULL, acc, 16);

    if (lane < 8) {
        out[(size_t)n * BB + b] = acc + bn;
    }
}

extern "C" void kernel_launch(void* const* d_in, const int* in_sizes, int n_in,
                              void* d_out, int out_size)
{
    // metadata order: x [N*B] f32, values [N*K] f32, bias [N] f32, indices [N*K] i32
    const float* x       = (const float*)d_in[0];
    const float* values  = (const float*)d_in[1];
    const float* bias    = (const float*)d_in[2];
    const int*   indices = (const int*)d_in[3];
    float*       out     = (float*)d_out;

    const int N = in_sizes[2];  // bias element count == number of neurons

    const int threads = 256;
    const int warps_per_block = threads / 32;
    const int blocks = (N + warps_per_block - 1) / warps_per_block;

    cortical_spmm_kernel<<<blocks, threads>>>(x, values, bias, indices, out, N);
}

// round 9
// speedup vs baseline: 1.8197x; 1.1064x over previous
#include <cuda_runtime.h>
#include <cstdint>

// CorticalSheet fixed-degree SpMM
//   out[n,b] = sum_k values[n,k] * x[indices[n,k], b] + bias[n]
// N from in_sizes (1,000,000), K = 32, B = 8
//
// R6 post-mortem: L1tex wavefront pipe binds at 85.7% util, ~45 slots/neuron
// against a 32-slot gather floor (one wavefront per random 32B row). The idle
// 14% is block churn + per-neuron serial ramp (streams -> gathers, ~500 cyc,
// one neuron per warp lifetime).
//
// This version: PERSISTENT GRID-STRIDE WARPS + cross-iteration prefetch.
//   - One warp processes ~170 neurons. Indices for neuron n+S are loaded
//     while neuron n's gathers are in flight; values(n)/bias(n) also overlap
//     the gather latency. A warp always has ~12 loads outstanding -> no ramp
//     bubbles, no block churn.
//   - Lane layout unchanged from R6 (measured best): lane = kgroup*8 + b,
//     lane self-loads its 8 (idx,val) as int4/float4 pairs (1 wavefront each,
//     in-line broadcast), 8 gather LDGs x 4 lines, shfl_xor(8)+(16) reduce,
//     lanes 0..7 store one 32B sector.
//   - __ldcs on all single-use streams (evict-first, protect x in L2),
//     __stcs on the write-once output, __ldg on x.
//   - __launch_bounds__(256, 5): 51-reg budget for the extra prefetch regs
//     without spilling; 40 warps/SM.

#define KK 32
#define BB 8

__global__ __launch_bounds__(256, 5)
void cortical_spmm_kernel(const float*  __restrict__ x,
                          const float*  __restrict__ values,
                          const float*  __restrict__ bias,
                          const int*    __restrict__ indices,
                          float*        __restrict__ out,
                          int N, int total_warps)
{
    const unsigned FULL = 0xffffffffu;
    const int warp_id = (int)((blockIdx.x * (unsigned)blockDim.x + threadIdx.x) >> 5);
    const int lane    = (int)(threadIdx.x & 31u);

    const int kgroup = lane >> 3;   // 0..3: owns k in [8*kgroup, 8*kgroup+8)
    const int b      = lane & 7;    // output column
    const int koff   = kgroup * 8;

    const float* xb = x + b;

    int n = warp_id;
    if (n >= N) return;

    // Prime the pipeline: indices for the first neuron.
    const int4* ip = (const int4*)(indices + (size_t)n * KK + koff);
    int4 iA0 = __ldcs(ip);
    int4 iA1 = __ldcs(ip + 1);

    while (true) {
        // ---- Issue the 8 gathers for neuron n (indices already resident).
        const float x0 = __ldg(xb + (size_t)iA0.x * BB);
        const float x1 = __ldg(xb + (size_t)iA0.y * BB);
        const float x2 = __ldg(xb + (size_t)iA0.z * BB);
        const float x3 = __ldg(xb + (size_t)iA0.w * BB);
        const float x4 = __ldg(xb + (size_t)iA1.x * BB);
        const float x5 = __ldg(xb + (size_t)iA1.y * BB);
        const float x6 = __ldg(xb + (size_t)iA1.z * BB);
        const float x7 = __ldg(xb + (size_t)iA1.w * BB);

        // ---- Overlap gather latency: prefetch next neuron's indices,
        //      and this neuron's values + bias.
        const int n_next = n + total_warps;
        const bool has_next = (n_next < N);
        int4 iB0, iB1;
        if (has_next) {
            const int4* ipn = (const int4*)(indices + (size_t)n_next * KK + koff);
            iB0 = __ldcs(ipn);
            iB1 = __ldcs(ipn + 1);
        }
        const float4* vp = (const float4*)(values + (size_t)n * KK + koff);
        const float4 v0 = __ldcs(vp);
        const float4 v1 = __ldcs(vp + 1);
        const float  bn = __ldcs(bias + n);

        // ---- Accumulate (waits on gathers + values).
        float acc = v0.x * x0;
        acc = fmaf(v0.y, x1, acc);
        acc = fmaf(v0.z, x2, acc);
        acc = fmaf(v0.w, x3, acc);
        acc = fmaf(v1.x, x4, acc);
        acc = fmaf(v1.y, x5, acc);
        acc = fmaf(v1.z, x6, acc);
        acc = fmaf(v1.w, x7, acc);

        // Reduce across the 4 kgroups (lanes b, b+8, b+16, b+24).
        acc += __shfl_xor_sync(FULL, acc, 8);
        acc += __shfl_xor_sync(FULL, acc, 16);

        if (lane < 8) {
            __stcs(out + (size_t)n * BB + b, acc + bn);
        }

        if (!has_next) break;
        n   = n_next;
        iA0 = iB0;
        iA1 = iB1;
    }
}

extern "C" void kernel_launch(void* const* d_in, const int* in_sizes, int n_in,
                              void* d_out, int out_size)
{
    // metadata order: x [N*B] f32, values [N*K] f32, bias [N] f32, indices [N*K] i32
    const float* x       = (const float*)d_in[0];
    const float* values  = (const float*)d_in[1];
    const float* bias    = (const float*)d_in[2];
    const int*   indices = (const int*)d_in[3];
    float*       out     = (float*)d_out;

    const int N = in_sizes[2];  // bias element count == number of neurons

    // Persistent-ish grid: 5 blocks/SM x 148 SMs, 8 warps each (clamped so
    // every launched warp has at least one neuron).
    const int threads = 256;
    const int warps_per_block = threads / 32;
    int blocks = 148 * 5;
    const int max_blocks = (N + warps_per_block - 1) / warps_per_block;
    if (blocks > max_blocks) blocks = max_blocks;
    const int total_warps = blocks * warps_per_block;

    cortical_spmm_kernel<<<blocks, threads>>>(x, values, bias, indices, out,
                                              N, total_warps);
}